// round 2
// baseline (speedup 1.0000x reference)
#include <cuda_runtime.h>
#include <cstdint>

// ---------------- problem constants ----------------
#define NN      100000      // nodes
#define EE      1600000     // edges per graph
#define IN_DIM  256
#define HD      42          // head dim
#define HPG     84          // heads*head_dim per GAT
#define NCOLS1  512         // padded 3*84+256=508 -> 512
#define OUTD    256
#define NEG     0.2f

// ---------------- static scratch (allocation-free) ----------------
__device__ float  d_HG[3ULL * NN * HPG];        // per-graph node features h  (33.6MB x3)
__device__ float  d_HCAT[(size_t)NN * NCOLS1];  // concat buffer, padded to 512
__device__ float  d_Wcat[IN_DIM * NCOLS1];      // packed [W1|W2|W3|W_self|0]
__device__ float  d_WP[NCOLS1 * OUTD];          // padded W_proj (508->512 rows)
__device__ float2 d_ASRC[3 * NN];
__device__ float2 d_ADST[3 * NN];
__device__ int    d_cnt[NN + 1];
__device__ int    d_off[NN + 1];
__device__ int    d_cur[NN];
__device__ int    d_csr[EE];

// ---------------- weight packing ----------------
__global__ void pack_w_kernel(const float* __restrict__ W1, const float* __restrict__ W2,
                              const float* __restrict__ W3, const float* __restrict__ Wself) {
    int idx = blockIdx.x * blockDim.x + threadIdx.x;
    if (idx >= IN_DIM * NCOLS1) return;
    int k = idx >> 9, n = idx & 511;
    float v;
    if (n < 84)       v = W1[k * 84 + n];
    else if (n < 168) v = W2[k * 84 + n - 84];
    else if (n < 252) v = W3[k * 84 + n - 168];
    else if (n < 508) v = Wself[k * 256 + (n - 252)];
    else              v = 0.f;
    d_Wcat[idx] = v;
}

__global__ void pack_wp_kernel(const float* __restrict__ Wproj) {
    int idx = blockIdx.x * blockDim.x + threadIdx.x;
    if (idx >= NCOLS1 * OUTD) return;
    int k = idx >> 8, n = idx & 255;
    d_WP[idx] = (k < 508) ? Wproj[k * 256 + n] : 0.f;
}

// ---------------- GEMM1: h_all = X @ Wcat  (100000x256 @ 256x512) ----------------
// BM=128 BN=64 BK=16, 256 threads, 8x4 micro-tile
__global__ __launch_bounds__(256) void gemm1_kernel(const float* __restrict__ X,
                                                    const float* __restrict__ bself) {
    __shared__ float As[16][136];
    __shared__ float Bs[16][64];
    int bx = blockIdx.x, by = blockIdx.y;
    int tid = threadIdx.x;
    int tx = tid & 15, ty = tid >> 4;
    int rowBase = by * 128;
    float acc[8][4];
#pragma unroll
    for (int i = 0; i < 8; i++)
#pragma unroll
        for (int j = 0; j < 4; j++) acc[i][j] = 0.f;

    for (int k0 = 0; k0 < IN_DIM; k0 += 16) {
#pragma unroll
        for (int q = 0; q < 2; q++) {
            int f = tid * 2 + q;
            int r = f >> 2, c4 = f & 3;
            int gm = rowBase + r;
            float4 v = make_float4(0.f, 0.f, 0.f, 0.f);
            if (gm < NN) v = *(const float4*)&X[(size_t)gm * IN_DIM + k0 + c4 * 4];
            As[c4 * 4 + 0][r] = v.x; As[c4 * 4 + 1][r] = v.y;
            As[c4 * 4 + 2][r] = v.z; As[c4 * 4 + 3][r] = v.w;
        }
        {
            int kr = tid >> 4, nc4 = tid & 15;
            float4 v = *(const float4*)&d_Wcat[(size_t)(k0 + kr) * NCOLS1 + bx * 64 + nc4 * 4];
            *(float4*)&Bs[kr][nc4 * 4] = v;
        }
        __syncthreads();
#pragma unroll
        for (int kk = 0; kk < 16; kk++) {
            float a[8], b[4];
            *(float4*)&a[0] = *(const float4*)&As[kk][ty * 8];
            *(float4*)&a[4] = *(const float4*)&As[kk][ty * 8 + 4];
            *(float4*)&b[0] = *(const float4*)&Bs[kk][tx * 4];
#pragma unroll
            for (int i = 0; i < 8; i++)
#pragma unroll
                for (int j = 0; j < 4; j++) acc[i][j] += a[i] * b[j];
        }
        __syncthreads();
    }
#pragma unroll
    for (int i = 0; i < 8; i++) {
        int m = rowBase + ty * 8 + i;
        if (m >= NN) break;
#pragma unroll
        for (int j = 0; j < 4; j++) {
            int n = bx * 64 + tx * 4 + j;
            float v = acc[i][j];
            if (n < 252) {
                int g = n / 84, jj = n - g * 84;
                d_HG[((size_t)g * NN + m) * HPG + jj] = v;
            } else if (n < 508) {
                d_HCAT[(size_t)m * NCOLS1 + n] = v + bself[n - 252];
            } else {
                d_HCAT[(size_t)m * NCOLS1 + n] = 0.f;
            }
        }
    }
}

// ---------------- attention scalars: a_src/a_dst per node per graph ----------------
// One kernel per graph (g passed in) — avoids runtime-indexed pointer arrays.
__global__ void attn_kernel(int g, const float* __restrict__ asv, const float* __restrict__ adv) {
    __shared__ float ssrc[HPG];
    __shared__ float sdst[HPG];
    int tid = threadIdx.x;
    if (tid < HPG) { ssrc[tid] = asv[tid]; sdst[tid] = adv[tid]; }
    __syncthreads();
    int warp = (blockIdx.x * blockDim.x + tid) >> 5;
    if (warp >= NN) return;
    int lane = tid & 31;
    const float* hr = d_HG + ((size_t)g * NN + warp) * HPG;
    float s0 = 0.f, s1 = 0.f, dd0 = 0.f, dd1 = 0.f;
#pragma unroll
    for (int t = 0; t < 3; t++) {
        int j = lane + 32 * t;
        if (j < HPG) {
            float h = hr[j];
            float vs = ssrc[j] * h, vd = sdst[j] * h;
            if (j < HD) { s0 += vs; dd0 += vd; }
            else        { s1 += vs; dd1 += vd; }
        }
    }
#pragma unroll
    for (int o = 16; o > 0; o >>= 1) {
        s0  += __shfl_xor_sync(0xffffffffu, s0, o);
        s1  += __shfl_xor_sync(0xffffffffu, s1, o);
        dd0 += __shfl_xor_sync(0xffffffffu, dd0, o);
        dd1 += __shfl_xor_sync(0xffffffffu, dd1, o);
    }
    if (lane == 0) {
        d_ASRC[g * NN + warp] = make_float2(s0, s1);
        d_ADST[g * NN + warp] = make_float2(dd0, dd1);
    }
}

// ---------------- CSR build ----------------
__global__ void zero_cnt_kernel() {
    int i = blockIdx.x * blockDim.x + threadIdx.x;
    if (i <= NN) d_cnt[i] = 0;
}

__global__ void hist_kernel(const int* __restrict__ ei) {
    int e = blockIdx.x * blockDim.x + threadIdx.x;
    if (e < EE) atomicAdd(&d_cnt[ei[EE + e]], 1);
}

__global__ __launch_bounds__(1024) void scan_kernel() {
    __shared__ int wsum[32];
    __shared__ int running_s;
    int tid = threadIdx.x, lane = tid & 31, w = tid >> 5;
    if (tid == 0) running_s = 0;
    __syncthreads();
    for (int base = 0; base < NN; base += 1024) {
        int i = base + tid;
        int v = (i < NN) ? d_cnt[i] : 0;
        int x = v;
#pragma unroll
        for (int o = 1; o < 32; o <<= 1) {
            int t = __shfl_up_sync(0xffffffffu, x, o);
            if (lane >= o) x += t;
        }
        if (lane == 31) wsum[w] = x;
        __syncthreads();
        if (w == 0) {
            int y = wsum[lane];
#pragma unroll
            for (int o = 1; o < 32; o <<= 1) {
                int t = __shfl_up_sync(0xffffffffu, y, o);
                if (lane >= o) y += t;
            }
            wsum[lane] = y;
        }
        __syncthreads();
        int warpOff = (w == 0) ? 0 : wsum[w - 1];
        int run = running_s;
        int excl = run + warpOff + x - v;
        if (i < NN) { d_off[i] = excl; d_cur[i] = excl; }
        __syncthreads();
        if (tid == 0) running_s += wsum[31];
        __syncthreads();
    }
    if (tid == 0) d_off[NN] = running_s;
}

__global__ void scatter_kernel(const int* __restrict__ ei) {
    int e = blockIdx.x * blockDim.x + threadIdx.x;
    if (e < EE) {
        int dst = ei[EE + e];
        int p = atomicAdd(&d_cur[dst], 1);
        d_csr[p] = ei[e];
    }
}

// ---------------- per-dst softmax + aggregation (warp per dst) ----------------
#define EXCAP 96
__global__ __launch_bounds__(256) void aggregate_kernel(int g, const float* __restrict__ bias) {
    __shared__ float2 exCache[8][EXCAP];
    int tid = threadIdx.x;
    int lane = tid & 31;
    int winb = tid >> 5;
    int d = (blockIdx.x * blockDim.x + tid) >> 5;
    if (d >= NN) return;

    const float* Hg = d_HG + (size_t)g * NN * HPG;
    const float2* asrc = d_ASRC + g * NN;
    float2 ad = d_ADST[g * NN + d];
    int beg = d_off[d], end = d_off[d + 1];

    // pass 1: S = sum exp(leakyrelu(a_src[s]+a_dst[d]))
    // alpha is bounded (|alpha| ~< 4), so the reference's max-shift is not needed
    // for fp32 stability: exp(a-m)/sum exp(a-m) == exp(a)/sum exp(a) exactly in math,
    // and both are well-conditioned here.
    float S0 = 0.f, S1 = 0.f;
    for (int e = beg + lane; e < end; e += 32) {
        int s = d_csr[e];
        float2 a = asrc[s];
        float a0 = a.x + ad.x; a0 = (a0 > 0.f) ? a0 : NEG * a0;
        float a1 = a.y + ad.y; a1 = (a1 > 0.f) ? a1 : NEG * a1;
        float e0 = __expf(a0), e1 = __expf(a1);
        int idx = e - beg;
        if (idx < EXCAP) exCache[winb][idx] = make_float2(e0, e1);
        S0 += e0; S1 += e1;
    }
#pragma unroll
    for (int o = 16; o > 0; o >>= 1) {
        S0 += __shfl_xor_sync(0xffffffffu, S0, o);
        S1 += __shfl_xor_sync(0xffffffffu, S1, o);
    }
    // self loop (reference appends arange(N) to both src and dst)
    float2 aself = asrc[d];
    float sa0 = aself.x + ad.x; sa0 = (sa0 > 0.f) ? sa0 : NEG * sa0;
    float sa1 = aself.y + ad.y; sa1 = (sa1 > 0.f) ? sa1 : NEG * sa1;
    float es0 = __expf(sa0), es1 = __expf(sa1);
    S0 += es0; S1 += es1;
    float r0 = 1.f / S0, r1 = 1.f / S1;

    // pass 2: weighted accumulation; lane handles features lane, lane+32, lane+64
    bool h2 = (lane >= 10);          // feature lane+32 belongs to head 1 iff lane+32 >= 42
    bool has3 = (lane < 20);         // feature lane+64 < 84
    const float* Hd = Hg + (size_t)d * HPG;
    float ws0 = es0 * r0, ws1 = es1 * r1;
    float acc0 = ws0 * Hd[lane];
    float acc1 = (h2 ? ws1 : ws0) * Hd[lane + 32];
    float acc2 = has3 ? ws1 * Hd[lane + 64] : 0.f;

    for (int e = beg; e < end; e++) {
        int s = d_csr[e];
        float w0, w1;
        int idx = e - beg;
        if (idx < EXCAP) {
            float2 ex = exCache[winb][idx];
            w0 = ex.x * r0; w1 = ex.y * r1;
        } else {
            float2 a = asrc[s];
            float a0 = a.x + ad.x; a0 = (a0 > 0.f) ? a0 : NEG * a0;
            float a1 = a.y + ad.y; a1 = (a1 > 0.f) ? a1 : NEG * a1;
            w0 = __expf(a0) * r0; w1 = __expf(a1) * r1;
        }
        const float* hs = Hg + (size_t)s * HPG;
        acc0 += w0 * hs[lane];
        acc1 += (h2 ? w1 : w0) * hs[lane + 32];
        if (has3) acc2 += w1 * hs[lane + 64];
    }
    float* outp = d_HCAT + (size_t)d * NCOLS1 + g * HPG;
    outp[lane]      = acc0 + bias[lane];
    outp[lane + 32] = acc1 + bias[lane + 32];
    if (has3) outp[lane + 64] = acc2 + bias[lane + 64];
}

// ---------------- GEMM2: out = HCAT @ WP + b_proj  (100000x512 @ 512x256) ----------------
__global__ __launch_bounds__(256) void gemm2_kernel(const float* __restrict__ bproj,
                                                    float* __restrict__ out) {
    __shared__ float As[16][136];
    __shared__ float Bs[16][64];
    int bx = blockIdx.x, by = blockIdx.y;
    int tid = threadIdx.x;
    int tx = tid & 15, ty = tid >> 4;
    int rowBase = by * 128;
    float acc[8][4];
#pragma unroll
    for (int i = 0; i < 8; i++)
#pragma unroll
        for (int j = 0; j < 4; j++) acc[i][j] = 0.f;

    for (int k0 = 0; k0 < NCOLS1; k0 += 16) {
#pragma unroll
        for (int q = 0; q < 2; q++) {
            int f = tid * 2 + q;
            int r = f >> 2, c4 = f & 3;
            int gm = rowBase + r;
            float4 v = make_float4(0.f, 0.f, 0.f, 0.f);
            if (gm < NN) v = *(const float4*)&d_HCAT[(size_t)gm * NCOLS1 + k0 + c4 * 4];
            As[c4 * 4 + 0][r] = v.x; As[c4 * 4 + 1][r] = v.y;
            As[c4 * 4 + 2][r] = v.z; As[c4 * 4 + 3][r] = v.w;
        }
        {
            int kr = tid >> 4, nc4 = tid & 15;
            float4 v = *(const float4*)&d_WP[(size_t)(k0 + kr) * OUTD + bx * 64 + nc4 * 4];
            *(float4*)&Bs[kr][nc4 * 4] = v;
        }
        __syncthreads();
#pragma unroll
        for (int kk = 0; kk < 16; kk++) {
            float a[8], b[4];
            *(float4*)&a[0] = *(const float4*)&As[kk][ty * 8];
            *(float4*)&a[4] = *(const float4*)&As[kk][ty * 8 + 4];
            *(float4*)&b[0] = *(const float4*)&Bs[kk][tx * 4];
#pragma unroll
            for (int i = 0; i < 8; i++)
#pragma unroll
                for (int j = 0; j < 4; j++) acc[i][j] += a[i] * b[j];
        }
        __syncthreads();
    }
#pragma unroll
    for (int i = 0; i < 8; i++) {
        int m = rowBase + ty * 8 + i;
        if (m >= NN) break;
#pragma unroll
        for (int j = 0; j < 4; j++) {
            int n = bx * 64 + tx * 4 + j;
            out[(size_t)m * OUTD + n] = acc[i][j] + bproj[n];
        }
    }
}

// ---------------- LayerNorm (in place on d_out), warp per row ----------------
__global__ void ln_kernel(float* __restrict__ out, const float* __restrict__ gamma,
                          const float* __restrict__ beta) {
    int warp = (blockIdx.x * blockDim.x + threadIdx.x) >> 5;
    if (warp >= NN) return;
    int lane = threadIdx.x & 31;
    float* row = out + (size_t)warp * OUTD;
    float v[8];
    float s = 0.f;
#pragma unroll
    for (int i = 0; i < 8; i++) { v[i] = row[lane + 32 * i]; s += v[i]; }
#pragma unroll
    for (int o = 16; o > 0; o >>= 1) s += __shfl_xor_sync(0xffffffffu, s, o);
    float mu = s * (1.f / 256.f);
    float var = 0.f;
#pragma unroll
    for (int i = 0; i < 8; i++) { float d = v[i] - mu; var += d * d; }
#pragma unroll
    for (int o = 16; o > 0; o >>= 1) var += __shfl_xor_sync(0xffffffffu, var, o);
    var *= (1.f / 256.f);
    float rs = rsqrtf(var + 1e-5f);
#pragma unroll
    for (int i = 0; i < 8; i++) {
        int f = lane + 32 * i;
        row[f] = (v[i] - mu) * rs * gamma[f] + beta[f];
    }
}

// ---------------- launch ----------------
extern "C" void kernel_launch(void* const* d_in, const int* in_sizes, int n_in,
                              void* d_out, int out_size) {
    (void)out_size;
    const float* x = (const float*)d_in[0];
    const int*   eidx[3];
    const float *W[3], *AS[3], *AD[3], *B[3];
    // Detect input ordering: signature order puts edge_index_2 at slot 2 (3.2M elems),
    // setup_inputs dict order puts W1 there (21504 elems).
    bool sig_order = (n_in >= 3 && in_sizes[2] == 2 * EE);
    if (sig_order) {
        // signature order: x, e1,e2,e3, (W,as,ad,b) x3, tail
        for (int g = 0; g < 3; g++) {
            eidx[g] = (const int*)d_in[1 + g];
            W[g]  = (const float*)d_in[4 + 4 * g + 0];
            AS[g] = (const float*)d_in[4 + 4 * g + 1];
            AD[g] = (const float*)d_in[4 + 4 * g + 2];
            B[g]  = (const float*)d_in[4 + 4 * g + 3];
        }
    } else {
        // dict order: x, (e,W,as,ad,b) x3, tail
        for (int g = 0; g < 3; g++) {
            eidx[g] = (const int*)d_in[1 + 5 * g + 0];
            W[g]  = (const float*)d_in[1 + 5 * g + 1];
            AS[g] = (const float*)d_in[1 + 5 * g + 2];
            AD[g] = (const float*)d_in[1 + 5 * g + 3];
            B[g]  = (const float*)d_in[1 + 5 * g + 4];
        }
    }
    const float* Wself = (const float*)d_in[16];
    const float* bself = (const float*)d_in[17];
    const float* Wproj = (const float*)d_in[18];
    const float* bproj = (const float*)d_in[19];
    const float* gamma = (const float*)d_in[20];
    const float* beta  = (const float*)d_in[21];
    float* out = (float*)d_out;

    pack_w_kernel<<<(IN_DIM * NCOLS1 + 255) / 256, 256>>>(W[0], W[1], W[2], Wself);
    pack_wp_kernel<<<(NCOLS1 * OUTD + 255) / 256, 256>>>(Wproj);

    dim3 g1(NCOLS1 / 64, (NN + 127) / 128);
    gemm1_kernel<<<g1, 256>>>(x, bself);

    for (int g = 0; g < 3; g++)
        attn_kernel<<<(NN + 7) / 8, 256>>>(g, AS[g], AD[g]);

    for (int g = 0; g < 3; g++) {
        zero_cnt_kernel<<<(NN + 256) / 256, 256>>>();
        hist_kernel<<<(EE + 255) / 256, 256>>>(eidx[g]);
        scan_kernel<<<1, 1024>>>();
        scatter_kernel<<<(EE + 255) / 256, 256>>>(eidx[g]);
        aggregate_kernel<<<(NN + 7) / 8, 256>>>(g, B[g]);
    }

    dim3 g2(OUTD / 64, (NN + 127) / 128);
    gemm2_kernel<<<g2, 256>>>(bproj, out);
    ln_kernel<<<(NN + 7) / 8, 256>>>(out, gamma, beta);
}

// round 9
// speedup vs baseline: 1.0933x; 1.0933x over previous
#include <cuda_runtime.h>
#include <cstdint>

// ---------------- problem constants ----------------
#define NN      100000
#define EE      1600000
#define IN_DIM  256
#define HD      42
#define HPG     84
#define NCOLS1  512       // padded 508 -> 512
#define OUTD    256
#define NEG     0.2f
#define NTOT3   (3*NN)
#define NSCB    ((NTOT3 + 1023)/1024)   // 293

// ---------------- static scratch ----------------
__device__ float  d_HG[3ULL * NN * HPG];
__device__ float  d_HCAT[(size_t)NN * NCOLS1];
__device__ float  d_Wcat[IN_DIM * NCOLS1];      // [k256][n512] packed [W1|W2|W3|W_self|0]
__device__ float  d_WP[NCOLS1 * OUTD];          // [k512][n256] padded W_proj
__device__ float2 d_ASRC[3 * NN];
__device__ float2 d_ADST[3 * NN];
__device__ int    d_cnt[NTOT3];
__device__ int    d_off[NTOT3 + 1];
__device__ int    d_cur[NTOT3];
__device__ int    d_csr[3 * EE];
__device__ int    d_part[NSCB];

// ---------------- weight packing (R2-proven) ----------------
__global__ void pack_w_kernel(const float* __restrict__ W1, const float* __restrict__ W2,
                              const float* __restrict__ W3, const float* __restrict__ Wself) {
    int idx = blockIdx.x * blockDim.x + threadIdx.x;
    if (idx >= IN_DIM * NCOLS1) return;
    int k = idx >> 9, n = idx & 511;
    float v;
    if (n < 84)       v = W1[k * 84 + n];
    else if (n < 168) v = W2[k * 84 + n - 84];
    else if (n < 252) v = W3[k * 84 + n - 168];
    else if (n < 508) v = Wself[k * 256 + (n - 252)];
    else              v = 0.f;
    d_Wcat[idx] = v;
}

__global__ void pack_wp_kernel(const float* __restrict__ Wproj) {
    int idx = blockIdx.x * blockDim.x + threadIdx.x;
    if (idx >= NCOLS1 * OUTD) return;
    int k = idx >> 8, n = idx & 255;
    d_WP[idx] = (k < 508) ? Wproj[k * 256 + n] : 0.f;
}

// ---------------- GEMM1 (R2-proven): h_all = X @ Wcat (100000x256 @ 256x512) ----------------
__global__ __launch_bounds__(256) void gemm1_kernel(const float* __restrict__ X,
                                                    const float* __restrict__ bself) {
    __shared__ float As[16][136];
    __shared__ float Bs[16][64];
    int bx = blockIdx.x, by = blockIdx.y;
    int tid = threadIdx.x;
    int tx = tid & 15, ty = tid >> 4;
    int rowBase = by * 128;
    float acc[8][4];
#pragma unroll
    for (int i = 0; i < 8; i++)
#pragma unroll
        for (int j = 0; j < 4; j++) acc[i][j] = 0.f;

    for (int k0 = 0; k0 < IN_DIM; k0 += 16) {
#pragma unroll
        for (int q = 0; q < 2; q++) {
            int f = tid * 2 + q;
            int r = f >> 2, c4 = f & 3;
            int gm = rowBase + r;
            float4 v = make_float4(0.f, 0.f, 0.f, 0.f);
            if (gm < NN) v = *(const float4*)&X[(size_t)gm * IN_DIM + k0 + c4 * 4];
            As[c4 * 4 + 0][r] = v.x; As[c4 * 4 + 1][r] = v.y;
            As[c4 * 4 + 2][r] = v.z; As[c4 * 4 + 3][r] = v.w;
        }
        {
            int kr = tid >> 4, nc4 = tid & 15;
            float4 v = *(const float4*)&d_Wcat[(size_t)(k0 + kr) * NCOLS1 + bx * 64 + nc4 * 4];
            *(float4*)&Bs[kr][nc4 * 4] = v;
        }
        __syncthreads();
#pragma unroll
        for (int kk = 0; kk < 16; kk++) {
            float a[8], b[4];
            *(float4*)&a[0] = *(const float4*)&As[kk][ty * 8];
            *(float4*)&a[4] = *(const float4*)&As[kk][ty * 8 + 4];
            *(float4*)&b[0] = *(const float4*)&Bs[kk][tx * 4];
#pragma unroll
            for (int i = 0; i < 8; i++)
#pragma unroll
                for (int j = 0; j < 4; j++) acc[i][j] += a[i] * b[j];
        }
        __syncthreads();
    }
#pragma unroll
    for (int i = 0; i < 8; i++) {
        int m = rowBase + ty * 8 + i;
        if (m >= NN) break;
#pragma unroll
        for (int j = 0; j < 4; j++) {
            int n = bx * 64 + tx * 4 + j;
            float v = acc[i][j];
            if (n < 252) {
                int g = n / 84, jj = n - g * 84;
                d_HG[((size_t)g * NN + m) * HPG + jj] = v;
            } else if (n < 508) {
                d_HCAT[(size_t)m * NCOLS1 + n] = v + bself[n - 252];
            } else {
                d_HCAT[(size_t)m * NCOLS1 + n] = 0.f;
            }
        }
    }
}

// ---------------- attention scalars (3 graphs via grid.y; scalar-only body) ----------------
__global__ void attn3_kernel(const float* __restrict__ as1, const float* __restrict__ ad1,
                             const float* __restrict__ as2, const float* __restrict__ ad2,
                             const float* __restrict__ as3, const float* __restrict__ ad3) {
    __shared__ float ssrc[HPG], sdst[HPG];
    int g = blockIdx.y;
    const float* asv = (g == 0) ? as1 : (g == 1) ? as2 : as3;
    const float* adv = (g == 0) ? ad1 : (g == 1) ? ad2 : ad3;
    int tid = threadIdx.x;
    if (tid < HPG) { ssrc[tid] = asv[tid]; sdst[tid] = adv[tid]; }
    __syncthreads();
    int warp = (blockIdx.x * blockDim.x + tid) >> 5;
    if (warp >= NN) return;
    int lane = tid & 31;
    const float* hr = d_HG + ((size_t)g * NN + warp) * HPG;
    float s0 = 0.f, s1 = 0.f, dd0 = 0.f, dd1 = 0.f;
#pragma unroll
    for (int t = 0; t < 3; t++) {
        int j = lane + 32 * t;
        if (j < HPG) {
            float h = hr[j];
            float vs = ssrc[j] * h, vd = sdst[j] * h;
            if (j < HD) { s0 += vs; dd0 += vd; }
            else        { s1 += vs; dd1 += vd; }
        }
    }
#pragma unroll
    for (int o = 16; o > 0; o >>= 1) {
        s0  += __shfl_xor_sync(0xffffffffu, s0, o);
        s1  += __shfl_xor_sync(0xffffffffu, s1, o);
        dd0 += __shfl_xor_sync(0xffffffffu, dd0, o);
        dd1 += __shfl_xor_sync(0xffffffffu, dd1, o);
    }
    if (lane == 0) {
        d_ASRC[g * NN + warp] = make_float2(s0, s1);
        d_ADST[g * NN + warp] = make_float2(dd0, dd1);
    }
}

// ---------------- merged CSR build (3 graphs concatenated; scalar-only kernels) ----------------
__device__ __forceinline__ const int* pick_e(int g, const int* e1, const int* e2, const int* e3) {
    return (g == 0) ? e1 : (g == 1) ? e2 : e3;
}

__global__ void zero3_kernel() {
    int i = blockIdx.x * blockDim.x + threadIdx.x;
    if (i < NTOT3) d_cnt[i] = 0;
}

__global__ void hist3_kernel(const int* e1, const int* e2, const int* e3) {
    int g = blockIdx.y;
    const int* ei = pick_e(g, e1, e2, e3);
    int e = blockIdx.x * blockDim.x + threadIdx.x;
    if (e < EE) atomicAdd(&d_cnt[g * NN + ei[EE + e]], 1);
}

__global__ __launch_bounds__(1024) void scan_p1_kernel() {
    __shared__ int ws[32];
    int tid = threadIdx.x, lane = tid & 31, w = tid >> 5;
    int i = blockIdx.x * 1024 + tid;
    int v = (i < NTOT3) ? d_cnt[i] : 0;
    int x = v;
#pragma unroll
    for (int o = 1; o < 32; o <<= 1) {
        int t = __shfl_up_sync(0xffffffffu, x, o);
        if (lane >= o) x += t;
    }
    if (lane == 31) ws[w] = x;
    __syncthreads();
    if (w == 0) {
        int y = ws[lane];
#pragma unroll
        for (int o = 1; o < 32; o <<= 1) {
            int t = __shfl_up_sync(0xffffffffu, y, o);
            if (lane >= o) y += t;
        }
        ws[lane] = y;
    }
    __syncthreads();
    int add = w ? ws[w - 1] : 0;
    if (i < NTOT3) d_off[i] = x + add - v;   // exclusive within tile
    if (tid == 0) d_part[blockIdx.x] = ws[31];
}

__global__ __launch_bounds__(512) void scan_p2_kernel() {
    __shared__ int ws[16];
    int tid = threadIdx.x, lane = tid & 31, w = tid >> 5;
    int v = (tid < NSCB) ? d_part[tid] : 0;
    int x = v;
#pragma unroll
    for (int o = 1; o < 32; o <<= 1) {
        int t = __shfl_up_sync(0xffffffffu, x, o);
        if (lane >= o) x += t;
    }
    if (lane == 31) ws[w] = x;
    __syncthreads();
    if (w == 0) {
        int y = (lane < 16) ? ws[lane] : 0;
#pragma unroll
        for (int o = 1; o < 32; o <<= 1) {
            int t = __shfl_up_sync(0xffffffffu, y, o);
            if (lane >= o) y += t;
        }
        if (lane < 16) ws[lane] = y;
    }
    __syncthreads();
    int add = w ? ws[w - 1] : 0;
    if (tid < NSCB) d_part[tid] = x + add - v;   // exclusive
}

__global__ __launch_bounds__(1024) void scan_p3_kernel() {
    int i = blockIdx.x * 1024 + threadIdx.x;
    if (i < NTOT3) {
        int off = d_off[i] + d_part[blockIdx.x];
        d_off[i] = off;
        d_cur[i] = off;
    }
    if (i == 0) d_off[NTOT3] = 3 * EE;
}

__global__ void scatter3_kernel(const int* e1, const int* e2, const int* e3) {
    int g = blockIdx.y;
    const int* ei = pick_e(g, e1, e2, e3);
    int e = blockIdx.x * blockDim.x + threadIdx.x;
    if (e < EE) {
        int dst = ei[EE + e];
        int p = atomicAdd(&d_cur[g * NN + dst], 1);
        d_csr[p] = ei[e];
    }
}

// ---------------- per-dst softmax + aggregation (warp per dst, 3 graphs) ----------------
#define EXCAP 96
__global__ __launch_bounds__(256) void aggregate3_kernel(const float* __restrict__ b1,
                                                         const float* __restrict__ b2,
                                                         const float* __restrict__ b3) {
    __shared__ float2 exCache[8][EXCAP];
    int g = blockIdx.y;
    const float* bias = (g == 0) ? b1 : (g == 1) ? b2 : b3;
    int tid = threadIdx.x;
    int lane = tid & 31;
    int winb = tid >> 5;
    int d = (blockIdx.x * blockDim.x + tid) >> 5;
    if (d >= NN) return;

    const float* Hg = d_HG + (size_t)g * NN * HPG;
    const float2* asrc = d_ASRC + g * NN;
    float2 ad = d_ADST[g * NN + d];
    int beg = d_off[g * NN + d], end = d_off[g * NN + d + 1];

    // pass 1: S = sum exp(leakyrelu(a_src[s]+a_dst[d]))  (alpha bounded; max-shift unnecessary)
    float S0 = 0.f, S1 = 0.f;
    for (int e = beg + lane; e < end; e += 32) {
        int s = d_csr[e];
        float2 a = asrc[s];
        float a0 = a.x + ad.x; a0 = (a0 > 0.f) ? a0 : NEG * a0;
        float a1 = a.y + ad.y; a1 = (a1 > 0.f) ? a1 : NEG * a1;
        float e0 = __expf(a0), e1 = __expf(a1);
        int idx = e - beg;
        if (idx < EXCAP) exCache[winb][idx] = make_float2(e0, e1);
        S0 += e0; S1 += e1;
    }
#pragma unroll
    for (int o = 16; o > 0; o >>= 1) {
        S0 += __shfl_xor_sync(0xffffffffu, S0, o);
        S1 += __shfl_xor_sync(0xffffffffu, S1, o);
    }
    float2 aself = asrc[d];
    float sa0 = aself.x + ad.x; sa0 = (sa0 > 0.f) ? sa0 : NEG * sa0;
    float sa1 = aself.y + ad.y; sa1 = (sa1 > 0.f) ? sa1 : NEG * sa1;
    float es0 = __expf(sa0), es1 = __expf(sa1);
    S0 += es0; S1 += es1;
    float r0 = 1.f / S0, r1 = 1.f / S1;

    bool h2 = (lane >= 10);
    bool has3 = (lane < 20);
    const float* Hd = Hg + (size_t)d * HPG;
    float ws0 = es0 * r0, ws1 = es1 * r1;
    float acc0 = ws0 * Hd[lane];
    float acc1 = (h2 ? ws1 : ws0) * Hd[lane + 32];
    float acc2 = has3 ? ws1 * Hd[lane + 64] : 0.f;

    for (int e = beg; e < end; e++) {
        int s = d_csr[e];
        float w0, w1;
        int idx = e - beg;
        if (idx < EXCAP) {
            float2 ex = exCache[winb][idx];
            w0 = ex.x * r0; w1 = ex.y * r1;
        } else {
            float2 a = asrc[s];
            float a0 = a.x + ad.x; a0 = (a0 > 0.f) ? a0 : NEG * a0;
            float a1 = a.y + ad.y; a1 = (a1 > 0.f) ? a1 : NEG * a1;
            w0 = __expf(a0) * r0; w1 = __expf(a1) * r1;
        }
        const float* hs = Hg + (size_t)s * HPG;
        acc0 += w0 * hs[lane];
        acc1 += (h2 ? w1 : w0) * hs[lane + 32];
        if (has3) acc2 += w1 * hs[lane + 64];
    }
    float* outp = d_HCAT + (size_t)d * NCOLS1 + g * HPG;
    outp[lane]      = acc0 + bias[lane];
    outp[lane + 32] = acc1 + bias[lane + 32];
    if (has3) outp[lane + 64] = acc2 + bias[lane + 64];
}

// ---------------- GEMM2 (R2-proven): out = HCAT @ WP + b_proj ----------------
__global__ __launch_bounds__(256) void gemm2_kernel(const float* __restrict__ bproj,
                                                    float* __restrict__ out) {
    __shared__ float As[16][136];
    __shared__ float Bs[16][64];
    int bx = blockIdx.x, by = blockIdx.y;
    int tid = threadIdx.x;
    int tx = tid & 15, ty = tid >> 4;
    int rowBase = by * 128;
    float acc[8][4];
#pragma unroll
    for (int i = 0; i < 8; i++)
#pragma unroll
        for (int j = 0; j < 4; j++) acc[i][j] = 0.f;

    for (int k0 = 0; k0 < NCOLS1; k0 += 16) {
#pragma unroll
        for (int q = 0; q < 2; q++) {
            int f = tid * 2 + q;
            int r = f >> 2, c4 = f & 3;
            int gm = rowBase + r;
            float4 v = make_float4(0.f, 0.f, 0.f, 0.f);
            if (gm < NN) v = *(const float4*)&d_HCAT[(size_t)gm * NCOLS1 + k0 + c4 * 4];
            As[c4 * 4 + 0][r] = v.x; As[c4 * 4 + 1][r] = v.y;
            As[c4 * 4 + 2][r] = v.z; As[c4 * 4 + 3][r] = v.w;
        }
        {
            int kr = tid >> 4, nc4 = tid & 15;
            float4 v = *(const float4*)&d_WP[(size_t)(k0 + kr) * OUTD + bx * 64 + nc4 * 4];
            *(float4*)&Bs[kr][nc4 * 4] = v;
        }
        __syncthreads();
#pragma unroll
        for (int kk = 0; kk < 16; kk++) {
            float a[8], b[4];
            *(float4*)&a[0] = *(const float4*)&As[kk][ty * 8];
            *(float4*)&a[4] = *(const float4*)&As[kk][ty * 8 + 4];
            *(float4*)&b[0] = *(const float4*)&Bs[kk][tx * 4];
#pragma unroll
            for (int i = 0; i < 8; i++)
#pragma unroll
                for (int j = 0; j < 4; j++) acc[i][j] += a[i] * b[j];
        }
        __syncthreads();
    }
#pragma unroll
    for (int i = 0; i < 8; i++) {
        int m = rowBase + ty * 8 + i;
        if (m >= NN) break;
#pragma unroll
        for (int j = 0; j < 4; j++) {
            int n = bx * 64 + tx * 4 + j;
            out[(size_t)m * OUTD + n] = acc[i][j] + bproj[n];
        }
    }
}

// ---------------- LayerNorm (R2-proven) ----------------
__global__ void ln_kernel(float* __restrict__ out, const float* __restrict__ gamma,
                          const float* __restrict__ beta) {
    int warp = (blockIdx.x * blockDim.x + threadIdx.x) >> 5;
    if (warp >= NN) return;
    int lane = threadIdx.x & 31;
    float* row = out + (size_t)warp * OUTD;
    float v[8];
    float s = 0.f;
#pragma unroll
    for (int i = 0; i < 8; i++) { v[i] = row[lane + 32 * i]; s += v[i]; }
#pragma unroll
    for (int o = 16; o > 0; o >>= 1) s += __shfl_xor_sync(0xffffffffu, s, o);
    float mu = s * (1.f / 256.f);
    float var = 0.f;
#pragma unroll
    for (int i = 0; i < 8; i++) { float d = v[i] - mu; var += d * d; }
#pragma unroll
    for (int o = 16; o > 0; o >>= 1) var += __shfl_xor_sync(0xffffffffu, var, o);
    var *= (1.f / 256.f);
    float rs = rsqrtf(var + 1e-5f);
#pragma unroll
    for (int i = 0; i < 8; i++) {
        int f = lane + 32 * i;
        row[f] = (v[i] - mu) * rs * gamma[f] + beta[f];
    }
}

// ---------------- launch ----------------
extern "C" void kernel_launch(void* const* d_in, const int* in_sizes, int n_in,
                              void* d_out, int out_size) {
    (void)out_size;
    const float* x = (const float*)d_in[0];
    const int*   eidx[3];
    const float *W[3], *AS[3], *AD[3], *B[3];
    bool sig_order = (n_in >= 3 && in_sizes[2] == 2 * EE);
    if (sig_order) {
        for (int g = 0; g < 3; g++) {
            eidx[g] = (const int*)d_in[1 + g];
            W[g]  = (const float*)d_in[4 + 4 * g + 0];
            AS[g] = (const float*)d_in[4 + 4 * g + 1];
            AD[g] = (const float*)d_in[4 + 4 * g + 2];
            B[g]  = (const float*)d_in[4 + 4 * g + 3];
        }
    } else {
        for (int g = 0; g < 3; g++) {
            eidx[g] = (const int*)d_in[1 + 5 * g + 0];
            W[g]  = (const float*)d_in[1 + 5 * g + 1];
            AS[g] = (const float*)d_in[1 + 5 * g + 2];
            AD[g] = (const float*)d_in[1 + 5 * g + 3];
            B[g]  = (const float*)d_in[1 + 5 * g + 4];
        }
    }
    const float* Wself = (const float*)d_in[16];
    const float* bself = (const float*)d_in[17];
    const float* Wproj = (const float*)d_in[18];
    const float* bproj = (const float*)d_in[19];
    const float* gamma = (const float*)d_in[20];
    const float* beta  = (const float*)d_in[21];
    float* out = (float*)d_out;

    pack_w_kernel<<<(IN_DIM * NCOLS1 + 255) / 256, 256>>>(W[0], W[1], W[2], Wself);
    pack_wp_kernel<<<(NCOLS1 * OUTD + 255) / 256, 256>>>(Wproj);

    // GEMM1: h_all = X @ [W1|W2|W3|W_self]
    dim3 g1(NCOLS1 / 64, (NN + 127) / 128);
    gemm1_kernel<<<g1, 256>>>(x, bself);

    // attention scalars (3 graphs)
    attn3_kernel<<<dim3((NN + 7) / 8, 3), 256>>>(AS[0], AD[0], AS[1], AD[1], AS[2], AD[2]);

    // CSR build for all 3 graphs, one concatenated multi-block scan
    zero3_kernel<<<(NTOT3 + 255) / 256, 256>>>();
    hist3_kernel<<<dim3((EE + 255) / 256, 3), 256>>>(eidx[0], eidx[1], eidx[2]);
    scan_p1_kernel<<<NSCB, 1024>>>();
    scan_p2_kernel<<<1, 512>>>();
    scan_p3_kernel<<<NSCB, 1024>>>();
    scatter3_kernel<<<dim3((EE + 255) / 256, 3), 256>>>(eidx[0], eidx[1], eidx[2]);

    // softmax + aggregate (3 graphs)
    aggregate3_kernel<<<dim3((NN + 7) / 8, 3), 256>>>(B[0], B[1], B[2]);

    // GEMM2 + LayerNorm
    dim3 g2(OUTD / 64, (NN + 127) / 128);
    gemm2_kernel<<<g2, 256>>>(bproj, out);
    ln_kernel<<<(NN + 7) / 8, 256>>>(out, gamma, beta);
}